// round 7
// baseline (speedup 1.0000x reference)
#include <cuda_runtime.h>

#define B_   128
#define S_   512
#define D_   256
#define H_   512
#define ODIM 1275

typedef unsigned long long u64;

// ---------------- persistent device scratch ----------------
__device__ __align__(16) float g_xT[S_ * D_ * B_];        // [t][d][b]
__device__ __align__(16) float g_W0p[128 * 768 * 16];     // [jtile][k][c], c = jj*4+gate
__device__ __align__(16) float g_W1p[128 * 1024 * 16];
__device__ __align__(16) float g_h0[2][H_ * B_];          // [buf][j][b]
__device__ __align__(16) float g_h1[2][H_ * B_];
__device__ unsigned g_bar_cnt = 0;
__device__ volatile unsigned g_bar_gen = 0;

// ---------------- f32x2 / fast-math helpers ----------------
__device__ __forceinline__ u64 pk2(float x, float y) {
    u64 r; asm("mov.b64 %0, {%1, %2};" : "=l"(r) : "f"(x), "f"(y)); return r;
}
__device__ __forceinline__ float2 up2(u64 v) {
    float2 r; asm("mov.b64 {%0, %1}, %2;" : "=f"(r.x), "=f"(r.y) : "l"(v)); return r;
}
__device__ __forceinline__ u64 add2(u64 a, u64 b) {
    u64 r; asm("add.rn.f32x2 %0, %1, %2;" : "=l"(r) : "l"(a), "l"(b)); return r;
}
#define FMA2(acc, a, b) asm("fma.rn.f32x2 %0, %1, %2, %0;" : "+l"(acc) : "l"(a), "l"(b))

__device__ __forceinline__ float ex2f(float x) {
    float y; asm("ex2.approx.ftz.f32 %0, %1;" : "=f"(y) : "f"(x)); return y;
}
__device__ __forceinline__ float rcpf(float x) {
    float y; asm("rcp.approx.ftz.f32 %0, %1;" : "=f"(y) : "f"(x)); return y;
}
__device__ __forceinline__ float fsig(float z) {
    return rcpf(1.f + ex2f(-1.44269504088896f * z));
}
__device__ __forceinline__ float ftanh(float z) {
    return 1.f - 2.f * rcpf(1.f + ex2f(2.88539008177793f * z));
}

// ---------------- cp.async ----------------
__device__ __forceinline__ void cp16(float4* dst, const float4* src) {
    unsigned d = (unsigned)__cvta_generic_to_shared(dst);
    asm volatile("cp.async.cg.shared.global [%0], [%1], 16;\n" :: "r"(d), "l"(src));
}
__device__ __forceinline__ void cp_commit() { asm volatile("cp.async.commit_group;\n" ::); }
__device__ __forceinline__ void cp_wait0()  { asm volatile("cp.async.wait_group 0;\n" ::); }

// ---------------- grid-wide barrier (all CTAs resident) ----------------
__device__ __forceinline__ void grid_sync(unsigned G) {
    __syncthreads();
    if (threadIdx.x == 0) {
        __threadfence();
        unsigned gen = g_bar_gen;
        if (atomicAdd(&g_bar_cnt, 1u) == G - 1u) {
            g_bar_cnt = 0;
            __threadfence();
            g_bar_gen = gen + 1u;
        } else {
            while (g_bar_gen == gen) { }
            __threadfence();
        }
    }
    __syncthreads();
}

// ---------------- prep: transpose x, pack weights per jtile ----------------
__global__ void prep_kernel(const float* __restrict__ x,
                            const float* __restrict__ W0,
                            const float* __restrict__ W1)
{
    const int stride = gridDim.x * blockDim.x;
    const int tid0 = blockIdx.x * blockDim.x + threadIdx.x;

    for (int idx = tid0; idx < S_ * D_ * B_; idx += stride) {
        int t = idx / (D_ * B_);
        int d = (idx / B_) % D_;
        int b = idx % B_;
        g_xT[idx] = x[(b * S_ + t) * D_ + d];
    }
    for (int idx = tid0; idx < 128 * 768 * 16; idx += stride) {
        int jt = idx / (768 * 16);
        int k  = (idx >> 4) % 768;
        int c  = idx & 15;
        g_W0p[idx] = W0[k * 2048 + (c & 3) * 512 + jt * 4 + (c >> 2)];
    }
    for (int idx = tid0; idx < 128 * 1024 * 16; idx += stride) {
        int jt = idx / (1024 * 16);
        int k  = (idx >> 4) % 1024;
        int c  = idx & 15;
        g_W1p[idx] = W1[k * 2048 + (c & 3) * 512 + jt * 4 + (c >> 2)];
    }
}

// ---------------- activation chunk prefetch (64 k-rows x 128 b, LINEAR dst) ----
__device__ __forceinline__ void prefetch_chunk(
    float4* s_act4, const float4* srcA, const float4* srcB, bool zeroB,
    int ch, int xch, int tid)
{
    float4* dst = s_act4 + ((ch & 1) << 11);
    if (ch < xch) {
        const float4* s = srcA + ((size_t)ch << 11);
        #pragma unroll
        for (int i = 0; i < 4; i++) { int idx = tid + (i << 9); cp16(dst + idx, s + idx); }
    } else if (zeroB) {
        float4 zz = make_float4(0.f, 0.f, 0.f, 0.f);
        #pragma unroll
        for (int i = 0; i < 4; i++) { int idx = tid + (i << 9); dst[idx] = zz; }
    } else {
        const float4* s = srcB + ((size_t)(ch - xch) << 11);
        #pragma unroll
        for (int i = 0; i < 4; i++) { int idx = tid + (i << 9); cp16(dst + idx, s + idx); }
    }
}

// ---------------- fused GEMM (FFMA2, K-split 8, 2-stage reduce) + gates --------
// 512 threads = 8 ksplit x (16 bt x 4 ct). Thread owns batch quads {bt, 16+bt}
// (batches 4bt..4bt+3, 64+4bt..64+4bt+3) x 4 gates of unit j0+ct.
// acc[q*4+g]: q=0:(4bt,4bt+1) q=1:(4bt+2,4bt+3) q=2:(64+4bt,+1) q=3:(64+4bt+2,+3)
__device__ __forceinline__ void do_phase(
    const float4* __restrict__ srcA, const float4* __restrict__ srcB, bool zeroB,
    int nch, int xch,
    const float4* __restrict__ s_w4,
    float4* s_act4, u64* s_ps, float* cstate, float* __restrict__ hout,
    float4 bias4,
    int tid, int ks, int r, int bt, int ct, int j0)
{
    u64 acc[16];
    #pragma unroll
    for (int i = 0; i < 16; i++) acc[i] = 0ull;

    prefetch_chunk(s_act4, srcA, srcB, zeroB, 0, xch, tid);
    cp_commit();

    for (int ch = 0; ch < nch; ch++) {
        cp_wait0();
        __syncthreads();
        if (ch + 1 < nch) {
            prefetch_chunk(s_act4, srcA, srcB, zeroB, ch + 1, xch, tid);
            cp_commit();
        }
        const float4* ab = s_act4 + ((ch & 1) << 11);
        const float4* wt = s_w4 + (ch << 8);

        // software pipeline over 8 k-steps (k = 8u + ks)
        float4 A0 = ab[(ks << 5) + bt];
        float4 A1 = ab[(ks << 5) + 16 + bt];
        float4 W  = wt[(ks << 2) + ct];
        #pragma unroll
        for (int u = 0; u < 8; u++) {
            float4 B0, B1, V;
            if (u < 7) {
                const int kn = ((u + 1) << 3) | ks;
                B0 = ab[(kn << 5) + bt];
                B1 = ab[(kn << 5) + 16 + bt];
                V  = wt[(kn << 2) + ct];
            }
            u64 p0 = pk2(A0.x, A0.y), p1 = pk2(A0.z, A0.w);
            u64 p2 = pk2(A1.x, A1.y), p3 = pk2(A1.z, A1.w);
            u64 s0 = pk2(W.x, W.x), s1 = pk2(W.y, W.y);
            u64 s2 = pk2(W.z, W.z), s3 = pk2(W.w, W.w);
            FMA2(acc[0],  p0, s0); FMA2(acc[1],  p0, s1); FMA2(acc[2],  p0, s2); FMA2(acc[3],  p0, s3);
            FMA2(acc[4],  p1, s0); FMA2(acc[5],  p1, s1); FMA2(acc[6],  p1, s2); FMA2(acc[7],  p1, s3);
            FMA2(acc[8],  p2, s0); FMA2(acc[9],  p2, s1); FMA2(acc[10], p2, s2); FMA2(acc[11], p2, s3);
            FMA2(acc[12], p3, s0); FMA2(acc[13], p3, s1); FMA2(acc[14], p3, s2); FMA2(acc[15], p3, s3);
            A0 = B0; A1 = B1; W = V;
        }
    }

    // ---- stage 1: fold ksplit 4..7 into 0..3 (pair ks <-> ks+4) ----
    if (ks >= 4) {
        #pragma unroll
        for (int a = 0; a < 16; a++)
            s_ps[a * 256 + ((ks - 4) << 6) + r] = acc[a];
    }
    __syncthreads();
    if (ks < 4) {
        #pragma unroll
        for (int a = 0; a < 16; a++)
            acc[a] = add2(acc[a], s_ps[a * 256 + (ks << 6) + r]);
    }
    __syncthreads();

    // ---- stage 2: 4-way exchange among ks 0..3: ps[q][wks][g][r] ----
    if (ks < 4) {
        #pragma unroll
        for (int q = 0; q < 4; q++) {
            if (q != ks) {
                #pragma unroll
                for (int g = 0; g < 4; g++)
                    s_ps[(((q << 2) + ks) << 2 | g) * 64 + r] = acc[(q << 2) + g];
            }
        }
    }
    __syncthreads();

    // ---- reduce own quarter + gate math: 2 batches x 4 gates (ks<4 only) ----
    if (ks < 4) {
        u64 z[4];
        #pragma unroll
        for (int g = 0; g < 4; g++) z[g] = acc[(ks << 2) + g];
        #pragma unroll
        for (int wks = 0; wks < 4; wks++) {
            if (wks != ks) {
                #pragma unroll
                for (int g = 0; g < 4; g++)
                    z[g] = add2(z[g], s_ps[(((ks << 2) + wks) << 2 | g) * 64 + r]);
            }
        }

        const int j = j0 + ct;
        const int b0 = (ks < 2) ? ((bt << 2) + (ks << 1))
                                : (64 + (bt << 2) + ((ks - 2) << 1));
        float2 zi = up2(z[0]), zf = up2(z[1]), zg = up2(z[2]), zo = up2(z[3]);

        float* cs = cstate + ct * 128 + b0;
        float2 c = *(float2*)cs;

        float siA = fsig(zi.x + bias4.x), sfA = fsig(zf.x + bias4.y);
        float tgA = ftanh(zg.x + bias4.z), soA = fsig(zo.x + bias4.w);
        float cnA = sfA * c.x + siA * tgA;
        float hA = soA * ftanh(cnA);

        float siB = fsig(zi.y + bias4.x), sfB = fsig(zf.y + bias4.y);
        float tgB = ftanh(zg.y + bias4.z), soB = fsig(zo.y + bias4.w);
        float cnB = sfB * c.y + siB * tgB;
        float hB = soB * ftanh(cnB);

        *(float2*)cs = make_float2(cnA, cnB);
        *(float2*)(hout + j * 128 + b0) = make_float2(hA, hB);
    }
    __syncthreads();   // ps reads done before next phase's writes
}

// ---------------- persistent main kernel: 128 CTAs x 512 threads ----------------
__global__ void __launch_bounds__(512, 1)
lstm_main(const float* __restrict__ b0g,
          const float* __restrict__ b1g,
          const float* __restrict__ Wp,
          const float* __restrict__ bp,
          float* __restrict__ out)
{
    extern __shared__ float smem[];
    float* s_w0  = smem;                    // 768*16   = 12288 floats
    float* s_w1  = s_w0 + 768 * 16;         // 1024*16  = 16384 floats
    float* s_act = s_w1 + 1024 * 16;        // 2*64*128 = 16384 floats
    float* s_psf = s_act + 16384;           // 4096 u64 = 8192 floats
    float* s_c0  = s_psf + 8192;            // 512
    float* s_c1  = s_c0 + 512;              // 512
    // total = 54272 floats = 217088 bytes

    const int tid = threadIdx.x;
    const unsigned G = gridDim.x;
    const int jt = blockIdx.x;
    const int j0 = jt * 4;
    const int ks = tid >> 6;      // 0..7
    const int r  = tid & 63;
    const int bt = r >> 2;        // 0..15
    const int ct = r & 3;         // 0..3

    // preload packed weights into smem (resident for entire kernel)
    {
        const float4* w0s = (const float4*)g_W0p + (size_t)jt * 768 * 4;
        const float4* w1s = (const float4*)g_W1p + (size_t)jt * 1024 * 4;
        float4* d0 = (float4*)s_w0;
        float4* d1 = (float4*)s_w1;
        for (int i = tid; i < 768 * 4; i += 512) d0[i] = w0s[i];
        for (int i = tid; i < 1024 * 4; i += 512) d1[i] = w1s[i];
    }
    for (int i = tid; i < 512; i += 512) { s_c0[i] = 0.f; s_c1[i] = 0.f; }
    __syncthreads();

    // per-thread biases in registers (gates i,f,g,o of unit j0+ct)
    const int jb = j0 + ct;
    const float4 bias0 = make_float4(b0g[jb], b0g[H_ + jb], b0g[2 * H_ + jb], b0g[3 * H_ + jb]);
    const float4 bias1 = make_float4(b1g[jb], b1g[H_ + jb], b1g[2 * H_ + jb], b1g[3 * H_ + jb]);

    float4* s_act4 = (float4*)s_act;
    u64*    s_ps   = (u64*)s_psf;
    const float4* s_w04 = (const float4*)s_w0;
    const float4* s_w14 = (const float4*)s_w1;

    for (int t = 0; t < S_; t++) {
        const int cur = t & 1, prv = cur ^ 1;

        // L0: act = [x_t (256 rows) | h0_prev (512 rows)], 12 chunks (4 from x)
        do_phase((const float4*)(g_xT + (size_t)t * D_ * B_),
                 (const float4*)g_h0[prv], t == 0, 12, 4,
                 s_w04, s_act4, s_ps, s_c0, g_h0[cur], bias0,
                 tid, ks, r, bt, ct, j0);

        grid_sync(G);   // h0(t) + h1(t-1) visible to all CTAs

        // L1: act = [h0_cur (512) | h1_prev (512)], 16 chunks (8 from h0)
        do_phase((const float4*)g_h0[cur],
                 (const float4*)g_h1[prv], t == 0, 16, 8,
                 s_w14, s_act4, s_ps, s_c1, g_h1[cur], bias1,
                 tid, ks, r, bt, ct, j0);
        // next step's L0 grid_sync orders L1(t) -> L1(t+1)
    }

    grid_sync(G);

    // ---- projection: out[b][m] = sum_k h1T[k][b] * Wp[k][m] + bp[m] ----
    {
        const float* h1f = g_h1[1];   // t = 511 -> cur = 1
        int mstart = jt * 10;
        int mend = mstart + 10; if (mend > ODIM) mend = ODIM;
        int b  = tid & 127;
        int mq = tid >> 7;            // 0..3
        for (int m = mstart + mq; m < mend; m += 4) {
            float acc = bp[m];
            #pragma unroll 4
            for (int k = 0; k < H_; k += 4) {
                acc += h1f[(k + 0) * 128 + b] * Wp[(k + 0) * ODIM + m];
                acc += h1f[(k + 1) * 128 + b] * Wp[(k + 1) * ODIM + m];
                acc += h1f[(k + 2) * 128 + b] * Wp[(k + 2) * ODIM + m];
                acc += h1f[(k + 3) * 128 + b] * Wp[(k + 3) * ODIM + m];
            }
            out[b * ODIM + m] = acc;
        }
    }
}

// ---------------- entry ----------------
extern "C" void kernel_launch(void* const* d_in, const int* in_sizes, int n_in,
                              void* d_out, int out_size)
{
    const float* x  = (const float*)d_in[0];
    const float* W0 = (const float*)d_in[1];
    const float* b0 = (const float*)d_in[2];
    const float* W1 = (const float*)d_in[3];
    const float* b1 = (const float*)d_in[4];
    const float* Wp = (const float*)d_in[5];
    const float* bp = (const float*)d_in[6];
    float* out = (float*)d_out;

    cudaFuncSetAttribute(lstm_main, cudaFuncAttributeMaxDynamicSharedMemorySize, 217088);

    prep_kernel<<<2048, 256>>>(x, W0, W1);
    lstm_main<<<128, 512, 217088>>>(b0, b1, Wp, bp, out);
}

// round 8
// speedup vs baseline: 1.1564x; 1.1564x over previous
#include <cuda_runtime.h>

#define B_   128
#define S_   512
#define D_   256
#define H_   512
#define ODIM 1275

typedef unsigned long long u64;

// ---------------- persistent device scratch ----------------
__device__ __align__(16) float g_xT[S_ * D_ * B_];        // [t][d][b]
__device__ __align__(16) float g_W0p[128 * 768 * 16];     // [jtile][k][c], c = jj*4+gate
__device__ __align__(16) float g_W1p[128 * 1024 * 16];
__device__ __align__(16) float g_h0[2][H_ * B_];          // [buf][j][b]
__device__ __align__(16) float g_h1[2][H_ * B_];
__device__ unsigned g_flags[128 * 32];                    // per-CTA barrier slot, 128B apart

// ---------------- f32x2 / fast-math helpers ----------------
__device__ __forceinline__ u64 pk2(float x, float y) {
    u64 r; asm("mov.b64 %0, {%1, %2};" : "=l"(r) : "f"(x), "f"(y)); return r;
}
__device__ __forceinline__ float2 up2(u64 v) {
    float2 r; asm("mov.b64 {%0, %1}, %2;" : "=f"(r.x), "=f"(r.y) : "l"(v)); return r;
}
__device__ __forceinline__ u64 add2(u64 a, u64 b) {
    u64 r; asm("add.rn.f32x2 %0, %1, %2;" : "=l"(r) : "l"(a), "l"(b)); return r;
}
#define FMA2(acc, a, b) asm("fma.rn.f32x2 %0, %1, %2, %0;" : "+l"(acc) : "l"(a), "l"(b))

__device__ __forceinline__ float ex2f(float x) {
    float y; asm("ex2.approx.ftz.f32 %0, %1;" : "=f"(y) : "f"(x)); return y;
}
__device__ __forceinline__ float rcpf(float x) {
    float y; asm("rcp.approx.ftz.f32 %0, %1;" : "=f"(y) : "f"(x)); return y;
}
__device__ __forceinline__ float fsig(float z) {
    return rcpf(1.f + ex2f(-1.44269504088896f * z));
}
__device__ __forceinline__ float ftanh(float z) {
    return 1.f - 2.f * rcpf(1.f + ex2f(2.88539008177793f * z));
}

// ---------------- cp.async ----------------
__device__ __forceinline__ void cp16(float4* dst, const float4* src) {
    unsigned d = (unsigned)__cvta_generic_to_shared(dst);
    asm volatile("cp.async.cg.shared.global [%0], [%1], 16;\n" :: "r"(d), "l"(src));
}
__device__ __forceinline__ void cp_commit() { asm volatile("cp.async.commit_group;\n" ::); }
__device__ __forceinline__ void cp_wait0()  { asm volatile("cp.async.wait_group 0;\n" ::); }

// ---------------- grid-wide barrier: per-CTA flag slots (no atomics) ----------
// Each CTA releases its own 128B-spaced slot with monotonic generation `gen`;
// threads 0..127 poll the 128 distinct slots in parallel (independent L2 lines).
__device__ __forceinline__ void grid_sync_flag(int jt, int tid, unsigned gen) {
    __syncthreads();
    if (tid == 0) {
        __threadfence();
        *((volatile unsigned*)&g_flags[jt * 32]) = gen;
    }
    if (tid < 128) {
        while (*((volatile unsigned*)&g_flags[tid * 32]) < gen) { }
    }
    __threadfence();
    __syncthreads();
}

// ---------------- prep: transpose x, pack weights per jtile ----------------
__global__ void prep_kernel(const float* __restrict__ x,
                            const float* __restrict__ W0,
                            const float* __restrict__ W1)
{
    const int stride = gridDim.x * blockDim.x;
    const int tid0 = blockIdx.x * blockDim.x + threadIdx.x;

    // reset barrier flags for graph replay determinism
    if (tid0 < 128 * 32) g_flags[tid0] = 0u;

    for (int idx = tid0; idx < S_ * D_ * B_; idx += stride) {
        int t = idx / (D_ * B_);
        int d = (idx / B_) % D_;
        int b = idx % B_;
        g_xT[idx] = x[(b * S_ + t) * D_ + d];
    }
    for (int idx = tid0; idx < 128 * 768 * 16; idx += stride) {
        int jt = idx / (768 * 16);
        int k  = (idx >> 4) % 768;
        int c  = idx & 15;
        g_W0p[idx] = W0[k * 2048 + (c & 3) * 512 + jt * 4 + (c >> 2)];
    }
    for (int idx = tid0; idx < 128 * 1024 * 16; idx += stride) {
        int jt = idx / (1024 * 16);
        int k  = (idx >> 4) % 1024;
        int c  = idx & 15;
        g_W1p[idx] = W1[k * 2048 + (c & 3) * 512 + jt * 4 + (c >> 2)];
    }
}

// ---------------- activation chunk prefetch (64 k-rows x 128 b, LINEAR dst) ----
__device__ __forceinline__ void prefetch_chunk(
    float4* s_act4, const float4* srcA, const float4* srcB, bool zeroB,
    int ch, int xch, int tid)
{
    float4* dst = s_act4 + ((ch & 1) << 11);
    if (ch < xch) {
        const float4* s = srcA + ((size_t)ch << 11);
        #pragma unroll
        for (int i = 0; i < 8; i++) { int idx = tid + (i << 8); cp16(dst + idx, s + idx); }
    } else if (zeroB) {
        float4 zz = make_float4(0.f, 0.f, 0.f, 0.f);
        #pragma unroll
        for (int i = 0; i < 8; i++) { int idx = tid + (i << 8); dst[idx] = zz; }
    } else {
        const float4* s = srcB + ((size_t)(ch - xch) << 11);
        #pragma unroll
        for (int i = 0; i < 8; i++) { int idx = tid + (i << 8); cp16(dst + idx, s + idx); }
    }
}

// ---------------- fused GEMM (FFMA2, K-split 4) + gates ----------------
// 256 threads = 4 ksplit x (16 bt x 4 ct). Thread owns batch quads {bt, 16+bt}
// (batches 4bt..4bt+3 and 64+4bt..64+4bt+3) x 4 gates of unit j0+ct.
// pf0: if false, chunk 0 was already prefetched+committed by the caller.
__device__ __forceinline__ void do_phase(
    const float4* __restrict__ srcA, const float4* __restrict__ srcB, bool zeroB,
    int nch, int xch, bool pf0,
    const float4* __restrict__ s_w4,
    float4* s_act4, u64* s_ps, float* cstate, float* __restrict__ hout,
    float4 bias4,
    int tid, int ks, int r, int bt, int ct, int j0)
{
    u64 acc[16];
    #pragma unroll
    for (int i = 0; i < 16; i++) acc[i] = 0ull;

    if (pf0) {
        prefetch_chunk(s_act4, srcA, srcB, zeroB, 0, xch, tid);
        cp_commit();
    }

    for (int ch = 0; ch < nch; ch++) {
        cp_wait0();
        __syncthreads();
        if (ch + 1 < nch) {
            prefetch_chunk(s_act4, srcA, srcB, zeroB, ch + 1, xch, tid);
            cp_commit();
        }
        const float4* ab = s_act4 + ((ch & 1) << 11);
        const float4* wt = s_w4 + (ch << 8);

        // software pipeline over 16 k-steps (k = 4u + ks)
        float4 A0 = ab[(ks << 5) + bt];
        float4 A1 = ab[(ks << 5) + 16 + bt];
        float4 W  = wt[(ks << 2) + ct];
        #pragma unroll
        for (int u = 0; u < 16; u++) {
            float4 B0, B1, V;
            if (u < 15) {
                const int kn = ((u + 1) << 2) | ks;
                B0 = ab[(kn << 5) + bt];
                B1 = ab[(kn << 5) + 16 + bt];
                V  = wt[(kn << 2) + ct];
            }
            u64 p0 = pk2(A0.x, A0.y), p1 = pk2(A0.z, A0.w);
            u64 p2 = pk2(A1.x, A1.y), p3 = pk2(A1.z, A1.w);
            u64 s0 = pk2(W.x, W.x), s1 = pk2(W.y, W.y);
            u64 s2 = pk2(W.z, W.z), s3 = pk2(W.w, W.w);
            FMA2(acc[0],  p0, s0); FMA2(acc[1],  p0, s1); FMA2(acc[2],  p0, s2); FMA2(acc[3],  p0, s3);
            FMA2(acc[4],  p1, s0); FMA2(acc[5],  p1, s1); FMA2(acc[6],  p1, s2); FMA2(acc[7],  p1, s3);
            FMA2(acc[8],  p2, s0); FMA2(acc[9],  p2, s1); FMA2(acc[10], p2, s2); FMA2(acc[11], p2, s3);
            FMA2(acc[12], p3, s0); FMA2(acc[13], p3, s1); FMA2(acc[14], p3, s2); FMA2(acc[15], p3, s3);
            A0 = B0; A1 = B1; W = V;
        }
    }

    // ---- exchange partials: ps[q][wks][g][r], r innermost -> conflict-free ----
    #pragma unroll
    for (int q = 0; q < 4; q++) {
        if (q != ks) {
            #pragma unroll
            for (int g = 0; g < 4; g++)
                s_ps[(((q << 2) + ks) << 2 | g) * 64 + r] = acc[(q << 2) + g];
        }
    }
    __syncthreads();

    // ---- reduce own quarter (q = ks) + gate math: 2 batches x 4 gates ----
    {
        u64 z[4];
        #pragma unroll
        for (int g = 0; g < 4; g++) z[g] = acc[(ks << 2) + g];
        #pragma unroll
        for (int wks = 0; wks < 4; wks++) {
            if (wks != ks) {
                #pragma unroll
                for (int g = 0; g < 4; g++)
                    z[g] = add2(z[g], s_ps[(((ks << 2) + wks) << 2 | g) * 64 + r]);
            }
        }

        const int j = j0 + ct;
        const int b0 = (ks < 2) ? ((bt << 2) + (ks << 1))
                                : (64 + (bt << 2) + ((ks - 2) << 1));
        float2 zi = up2(z[0]), zf = up2(z[1]), zg = up2(z[2]), zo = up2(z[3]);

        float* cs = cstate + ct * 128 + b0;
        float2 c = *(float2*)cs;

        float siA = fsig(zi.x + bias4.x), sfA = fsig(zf.x + bias4.y);
        float tgA = ftanh(zg.x + bias4.z), soA = fsig(zo.x + bias4.w);
        float cnA = sfA * c.x + siA * tgA;
        float hA = soA * ftanh(cnA);

        float siB = fsig(zi.y + bias4.x), sfB = fsig(zf.y + bias4.y);
        float tgB = ftanh(zg.y + bias4.z), soB = fsig(zo.y + bias4.w);
        float cnB = sfB * c.y + siB * tgB;
        float hB = soB * ftanh(cnB);

        *(float2*)cs = make_float2(cnA, cnB);
        *(float2*)(hout + j * 128 + b0) = make_float2(hA, hB);
    }
    __syncthreads();   // ps reads done before next phase's writes
}

// ---------------- persistent main kernel: 128 CTAs x 256 threads ----------------
__global__ void __launch_bounds__(256, 1)
lstm_main(const float* __restrict__ b0g,
          const float* __restrict__ b1g,
          const float* __restrict__ Wp,
          const float* __restrict__ bp,
          float* __restrict__ out)
{
    extern __shared__ float smem[];
    float* s_w0  = smem;                    // 768*16   = 12288 floats
    float* s_w1  = s_w0 + 768 * 16;         // 1024*16  = 16384 floats
    float* s_act = s_w1 + 1024 * 16;        // 2*64*128 = 16384 floats
    float* s_psf = s_act + 16384;           // 4096 u64 = 8192 floats
    float* s_c0  = s_psf + 8192;            // 512
    float* s_c1  = s_c0 + 512;              // 512
    // total = 54272 floats = 217088 bytes

    const int tid = threadIdx.x;
    const int jt = blockIdx.x;
    const int j0 = jt * 4;
    const int ks = tid >> 6;      // 0..3
    const int r  = tid & 63;
    const int bt = r >> 2;        // 0..15
    const int ct = r & 3;         // 0..3

    // preload packed weights into smem (resident for entire kernel)
    {
        const float4* w0s = (const float4*)g_W0p + (size_t)jt * 768 * 4;
        const float4* w1s = (const float4*)g_W1p + (size_t)jt * 1024 * 4;
        float4* d0 = (float4*)s_w0;
        float4* d1 = (float4*)s_w1;
        for (int i = tid; i < 768 * 4; i += 256) d0[i] = w0s[i];
        for (int i = tid; i < 1024 * 4; i += 256) d1[i] = w1s[i];
    }
    for (int i = tid; i < 512; i += 256) { s_c0[i] = 0.f; s_c1[i] = 0.f; }
    __syncthreads();

    // per-thread biases in registers (gates i,f,g,o of unit j0+ct)
    const int jb = j0 + ct;
    const float4 bias0 = make_float4(b0g[jb], b0g[H_ + jb], b0g[2 * H_ + jb], b0g[3 * H_ + jb]);
    const float4 bias1 = make_float4(b1g[jb], b1g[H_ + jb], b1g[2 * H_ + jb], b1g[3 * H_ + jb]);

    float4* s_act4 = (float4*)s_act;
    u64*    s_ps   = (u64*)s_psf;
    const float4* s_w04 = (const float4*)s_w0;
    const float4* s_w14 = (const float4*)s_w1;

    for (int t = 0; t < S_; t++) {
        const int cur = t & 1, prv = cur ^ 1;

        // L0: act = [x_t (256 rows) | h0_prev (512 rows)], 12 chunks (4 from x).
        // For t>0, chunk 0 (x) was prefetched during the previous step's L1 epilogue.
        do_phase((const float4*)(g_xT + (size_t)t * D_ * B_),
                 (const float4*)g_h0[prv], t == 0, 12, 4, /*pf0=*/(t == 0),
                 s_w04, s_act4, s_ps, s_c0, g_h0[cur], bias0,
                 tid, ks, r, bt, ct, j0);

        grid_sync_flag(jt, tid, (unsigned)(t + 1));   // h0(t) + h1(t-1) visible everywhere

        // L1: act = [h0_cur (512) | h1_prev (512)], 16 chunks (8 from h0)
        do_phase((const float4*)g_h0[cur],
                 (const float4*)g_h1[prv], t == 0, 16, 8, /*pf0=*/true,
                 s_w14, s_act4, s_ps, s_c1, g_h1[cur], bias1,
                 tid, ks, r, bt, ct, j0);

        // early prefetch of next step's x chunk 0 into act buffer 0 (input-only, no hazard)
        if (t + 1 < S_) {
            prefetch_chunk(s_act4, (const float4*)(g_xT + (size_t)(t + 1) * D_ * B_),
                           (const float4*)g_h0[cur], false, 0, 4, tid);
            cp_commit();
        }
        // next step's L0 grid_sync orders L1(t) -> L1(t+1)
    }

    grid_sync_flag(jt, tid, (unsigned)(S_ + 1));

    // ---- projection: out[b][m] = sum_k h1T[k][b] * Wp[k][m] + bp[m] ----
    {
        const float* h1f = g_h1[1];   // t = 511 -> cur = 1
        int mstart = jt * 10;
        int mend = mstart + 10; if (mend > ODIM) mend = ODIM;
        int b  = tid & 127;
        int mq = tid >> 7;            // 0..1
        for (int m = mstart + mq; m < mend; m += 2) {
            float acc = bp[m];
            #pragma unroll 4
            for (int k = 0; k < H_; k += 4) {
                acc += h1f[(k + 0) * 128 + b] * Wp[(k + 0) * ODIM + m];
                acc += h1f[(k + 1) * 128 + b] * Wp[(k + 1) * ODIM + m];
                acc += h1f[(k + 2) * 128 + b] * Wp[(k + 2) * ODIM + m];
                acc += h1f[(k + 3) * 128 + b] * Wp[(k + 3) * ODIM + m];
            }
            out[b * ODIM + m] = acc;
        }
    }
}

// ---------------- entry ----------------
extern "C" void kernel_launch(void* const* d_in, const int* in_sizes, int n_in,
                              void* d_out, int out_size)
{
    const float* x  = (const float*)d_in[0];
    const float* W0 = (const float*)d_in[1];
    const float* b0 = (const float*)d_in[2];
    const float* W1 = (const float*)d_in[3];
    const float* b1 = (const float*)d_in[4];
    const float* Wp = (const float*)d_in[5];
    const float* bp = (const float*)d_in[6];
    float* out = (float*)d_out;

    cudaFuncSetAttribute(lstm_main, cudaFuncAttributeMaxDynamicSharedMemorySize, 217088);

    prep_kernel<<<2048, 256>>>(x, W0, W1);
    lstm_main<<<128, 256, 217088>>>(b0, b1, Wp, bp, out);
}